// round 7
// baseline (speedup 1.0000x reference)
#include <cuda_runtime.h>
#include <cuda_fp16.h>
#include <cstdint>
#include <math.h>

// ============================================================================
// VectorQuantizer — base-target ISA (mma.sync m16n8k16 + ldmatrix + cp.async)
//   N = 262144 rows, D = 64, K = 1024 codes.
//   key_k = dot(xn, cn_k) - 0.5*||cn_k||^2   (argmax == reference argmin)
//   fp16 HMMA scores + per-row top-12 candidates + fp64 rescue of tight rows.
//   M=256 rows per CTA, 8 warps x m32 (B-fragment reuse), ldmatrix fragments.
// ============================================================================

#define NROWS   262144
#define DIM     64
#define KCODES  1024
#define NQ      16777216
#define MTILE   256
#define NCTAS   1024               // NROWS / MTILE
#define THRESH  2e-3f

// ---- device scratch ----
__device__ __align__(16) __half  g_bh[KCODES * DIM];   // normalized codebook fp16
__device__ __align__(16) float   g_cnf[KCODES * DIM];  // normalized codebook fp32
__device__ double                g_biasd[KCODES];      // 0.5*||cn||^2 fp64
__device__ float                 g_biasf[KCODES];      // 0.5*||cn||^2 fp32
__device__ float                 g_partials[NCTAS];

// ---- smem layout (bytes) ----
#define SM_B     0          // 2 x (128 codes x 144B)    = 36864
#define SM_A     36864      // 256 rows x 144B           = 36864
#define SM_BIAS  73728      // 1024 floats               = 4096
#define SM_RN    77824      // 256 floats                = 1024
#define SM_ISW   78848      // 256 ints                  = 1024
#define SM_LIST  79872      // 256 ints                  = 1024
#define SM_CAND  80896      // 256 x 12 uint16           = 6144
#define SM_CNT   87040      // 16
#define SM_RED   87056      // 32
#define SM_TOTAL 87104

// ---- PTX helpers ----
__device__ __forceinline__ void mma16816(float c[4], const uint32_t a[4],
                                         uint32_t b0, uint32_t b1) {
    asm volatile(
        "mma.sync.aligned.m16n8k16.row.col.f32.f16.f16.f32 "
        "{%0,%1,%2,%3}, {%4,%5,%6,%7}, {%8,%9}, {%0,%1,%2,%3};"
        : "+f"(c[0]), "+f"(c[1]), "+f"(c[2]), "+f"(c[3])
        : "r"(a[0]), "r"(a[1]), "r"(a[2]), "r"(a[3]), "r"(b0), "r"(b1));
}
__device__ __forceinline__ void ldm4(uint32_t addr, uint32_t& r0, uint32_t& r1,
                                     uint32_t& r2, uint32_t& r3) {
    asm volatile("ldmatrix.sync.aligned.m8n8.x4.shared.b16 {%0,%1,%2,%3}, [%4];"
                 : "=r"(r0), "=r"(r1), "=r"(r2), "=r"(r3) : "r"(addr));
}
__device__ __forceinline__ uint32_t smem_u32(const void* p) {
    uint32_t a;
    asm("{ .reg .u64 t; cvta.to.shared.u64 t, %1; cvt.u32.u64 %0, t; }"
        : "=r"(a) : "l"(p));
    return a;
}
__device__ __forceinline__ void cp16(uint32_t dst, const void* src) {
    asm volatile("cp.async.cg.shared.global [%0], [%1], 16;"
                 :: "r"(dst), "l"(src) : "memory");
}
__device__ __forceinline__ void cp_commit() {
    asm volatile("cp.async.commit_group;" ::: "memory");
}
__device__ __forceinline__ void cp_wait1() {
    asm volatile("cp.async.wait_group 1;" ::: "memory");
}
__device__ __forceinline__ void cp_wait0() {
    asm volatile("cp.async.wait_group 0;" ::: "memory");
}

// sorted top-3 insert (strict >, earliest index wins ties)
__device__ __forceinline__ void ins3(float* v, int* ix, float s, int k) {
    if (s > v[2]) {
        if (s > v[1]) {
            v[2] = v[1]; ix[2] = ix[1];
            if (s > v[0]) { v[1] = v[0]; ix[1] = ix[0]; v[0] = s; ix[0] = k; }
            else          { v[1] = s; ix[1] = k; }
        } else { v[2] = s; ix[2] = k; }
    }
}
// batch-filtered: 4 scores at cols k0, k0+1, k0+8, k0+9
__device__ __forceinline__ void filt4(float* v, int* ix,
                                      float s0, float s1, float s2, float s3,
                                      int k0) {
    float mx = fmaxf(fmaxf(s0, s1), fmaxf(s2, s3));
    if (mx > v[2]) {
        ins3(v, ix, s0, k0);
        ins3(v, ix, s1, k0 + 1);
        ins3(v, ix, s2, k0 + 8);
        ins3(v, ix, s3, k0 + 9);
    }
}

// ============================================================================
// Kernel 1: codebook prep — warp per code
// ============================================================================
__global__ void vq_prep(const float* __restrict__ cb) {
    int wid  = threadIdx.x >> 5;
    int lane = threadIdx.x & 31;
    int k = blockIdx.x * 8 + wid;
    float2 v = ((const float2*)(cb + (size_t)k * DIM))[lane];
    float s = v.x * v.x + v.y * v.y;
    #pragma unroll
    for (int o = 16; o > 0; o >>= 1) s += __shfl_xor_sync(0xffffffffu, s, o);
    float n = fmaxf(sqrtf(s), 1e-12f);
    float a0 = v.x / n, a1 = v.y / n;
    ((float2*)(g_cnf + (size_t)k * DIM))[lane] = make_float2(a0, a1);
    ((__half2*)(g_bh + (size_t)k * DIM))[lane] =
        __halves2half2(__float2half_rn(a0), __float2half_rn(a1));
    double bd = (double)a0 * (double)a0 + (double)a1 * (double)a1;
    #pragma unroll
    for (int o = 16; o > 0; o >>= 1) bd += __shfl_xor_sync(0xffffffffu, bd, o);
    if (lane == 0) {
        g_biasd[k] = 0.5 * bd;
        g_biasf[k] = (float)(0.5 * bd);
    }
}

// ============================================================================
// Kernel 2: GEMM + argmax + rescue + outputs.  256 rows/CTA, 8 warps x m32.
// ============================================================================
__global__ void __launch_bounds__(256, 2)
vq_main(const float* __restrict__ x, const float* __restrict__ cb,
        float* __restrict__ out) {
    extern __shared__ char smem[];
    const uint32_t sb = smem_u32(smem);
    const int tid  = threadIdx.x;
    const int wid  = tid >> 5;
    const int lane = tid & 31;
    const int row0 = blockIdx.x * MTILE;

    float*    bsm  = (float*)(smem + SM_BIAS);
    float*    rnsm = (float*)(smem + SM_RN);
    int*      isw  = (int*)(smem + SM_ISW);
    int*      list = (int*)(smem + SM_LIST);
    uint16_t* cand = (uint16_t*)(smem + SM_CAND);
    int*      cnt  = (int*)(smem + SM_CNT);
    float*    red  = (float*)(smem + SM_RED);

    if (tid == 0) *cnt = 0;

    // ---- prefetch B chunks 0,1 via cp.async (overlaps with norm phase) ----
    const __half* bh = g_bh;
    #pragma unroll
    for (int pc = 0; pc < 2; pc++) {
        #pragma unroll
        for (int i = 0; i < 4; i++) {
            int idx = tid + i * 256;          // 0..1023
            int r = idx >> 3, seg = idx & 7;
            cp16(sb + SM_B + pc * 18432 + r * 144 + seg * 16,
                 bh + ((size_t)(pc * 128 + r)) * DIM + seg * 8);
        }
        cp_commit();
    }

    // ---- bias to smem ----
    #pragma unroll
    for (int i = 0; i < 4; i++) { int g0 = tid + i * 256; bsm[g0] = g_biasf[g0]; }

    // ---- norms + fp16 A rows (warp per row, gmem-direct) ----
    #pragma unroll 4
    for (int j = 0; j < 32; j++) {
        int r = wid + 8 * j;                  // 0..255
        float2 v = ((const float2*)(x + (size_t)(row0 + r) * DIM))[lane];
        float s = v.x * v.x + v.y * v.y;
        #pragma unroll
        for (int o = 16; o > 0; o >>= 1) s += __shfl_xor_sync(0xffffffffu, s, o);
        float n = fmaxf(sqrtf(s), 1e-12f);
        if (lane == 0) rnsm[r] = n;
        *(__half2*)(smem + SM_A + r * 144 + lane * 4) =
            __halves2half2(__float2half_rn(v.x / n), __float2half_rn(v.y / n));
    }
    __syncthreads();

    // ---- A fragments via ldmatrix (persist in registers) ----
    const int lr = lane & 7, m = lane >> 3;
    const int Rb = wid * 32;
    const uint32_t a_loff = (uint32_t)((lr + (m & 1) * 8) * 144 + (m >> 1) * 16);
    const uint32_t b_loff = (uint32_t)(((m >> 1) * 8 + lr) * 144 + (m & 1) * 16);
    uint32_t afr[2][4][4];
    #pragma unroll
    for (int t = 0; t < 2; t++)
        #pragma unroll
        for (int ks = 0; ks < 4; ks++)
            ldm4(sb + SM_A + (uint32_t)((Rb + t * 16) * 144 + ks * 32) + a_loff,
                 afr[t][ks][0], afr[t][ks][1], afr[t][ks][2], afr[t][ks][3]);

    // ---- main loop: 8 chunks of 128 codes, double-buffered ----
    float v0[3] = {-1e30f,-1e30f,-1e30f}, v1[3] = {-1e30f,-1e30f,-1e30f};
    float v2[3] = {-1e30f,-1e30f,-1e30f}, v3[3] = {-1e30f,-1e30f,-1e30f};
    int   i0[3] = {0,0,0}, i1[3] = {0,0,0}, i2[3] = {0,0,0}, i3[3] = {0,0,0};
    const int c = lane & 3;

    #pragma unroll 1
    for (int ch = 0; ch < 8; ch++) {
        if (ch == 7) cp_wait0(); else cp_wait1();
        __syncthreads();
        const uint32_t Bb = sb + SM_B + (uint32_t)((ch & 1) * 18432) + b_loff;
        const int cb0 = ch * 128 + 2 * c;

        #pragma unroll
        for (int nbp = 0; nbp < 8; nbp++) {
            uint32_t bk[4][4];
            #pragma unroll
            for (int ks = 0; ks < 4; ks++)
                ldm4(Bb + (uint32_t)(nbp * 2304 + ks * 32),
                     bk[ks][0], bk[ks][1], bk[ks][2], bk[ks][3]);
            float a00[4] = {0,0,0,0}, a01[4] = {0,0,0,0};
            float a10[4] = {0,0,0,0}, a11[4] = {0,0,0,0};
            #pragma unroll
            for (int ks = 0; ks < 4; ks++) {
                mma16816(a00, afr[0][ks], bk[ks][0], bk[ks][1]);
                mma16816(a01, afr[0][ks], bk[ks][2], bk[ks][3]);
                mma16816(a10, afr[1][ks], bk[ks][0], bk[ks][1]);
                mma16816(a11, afr[1][ks], bk[ks][2], bk[ks][3]);
            }
            int col0 = cb0 + nbp * 16;
            float2 bb0 = *(const float2*)(bsm + col0);
            float2 bb1 = *(const float2*)(bsm + col0 + 8);
            filt4(v0, i0, a00[0]-bb0.x, a00[1]-bb0.y, a01[0]-bb1.x, a01[1]-bb1.y, col0);
            filt4(v1, i1, a00[2]-bb0.x, a00[3]-bb0.y, a01[2]-bb1.x, a01[3]-bb1.y, col0);
            filt4(v2, i2, a10[0]-bb0.x, a10[1]-bb0.y, a11[0]-bb1.x, a11[1]-bb1.y, col0);
            filt4(v3, i3, a10[2]-bb0.x, a10[3]-bb0.y, a11[2]-bb1.x, a11[3]-bb1.y, col0);
        }
        __syncthreads();
        if (ch < 6) {                          // prefetch chunk ch+2
            int pc = ch + 2;
            #pragma unroll
            for (int i = 0; i < 4; i++) {
                int idx = tid + i * 256;
                int r = idx >> 3, seg = idx & 7;
                cp16(sb + SM_B + (pc & 1) * 18432 + r * 144 + seg * 16,
                     bh + ((size_t)(pc * 128 + r)) * DIM + seg * 8);
            }
            cp_commit();
        }
    }

    // ---- quad merge: row best / margin / candidate dump ----
    const int g = lane >> 2;
    #pragma unroll
    for (int h = 0; h < 4; h++) {
        float* v  = (h == 0) ? v0 : (h == 1) ? v1 : (h == 2) ? v2 : v3;
        int*   iv = (h == 0) ? i0 : (h == 1) ? i1 : (h == 2) ? i2 : i3;
        int row = Rb + (h >> 1) * 16 + (h & 1) * 8 + g;
        float bs = v[0]; int bi = iv[0];
        #pragma unroll
        for (int off = 1; off <= 2; off <<= 1) {
            float os = __shfl_xor_sync(0xffffffffu, bs, off);
            int   oi = __shfl_xor_sync(0xffffffffu, bi, off);
            if (os > bs || (os == bs && oi < bi)) { bs = os; bi = oi; }
        }
        float s2 = (iv[0] == bi) ? v[1] : v[0];
        #pragma unroll
        for (int off = 1; off <= 2; off <<= 1)
            s2 = fmaxf(s2, __shfl_xor_sync(0xffffffffu, s2, off));
        #pragma unroll
        for (int j = 0; j < 3; j++)
            cand[row * 12 + 3 * c + j] = (uint16_t)iv[j];
        if (c == 0) {
            isw[row] = bi;
            if (bs - s2 < THRESH) { int p = atomicAdd(cnt, 1); list[p] = row; }
        }
    }
    __syncthreads();

    // ---- fp64 rescue of tight rows (12 candidates each, warp per row) ----
    int nflag = *cnt;
    for (int e = wid; e < nflag; e += 8) {
        int row = list[e];
        double sc = -1e300; int kk = 0x7fffffff;
        if (lane < 12) {
            kk = (int)cand[row * 12 + lane];
            float rn = rnsm[row];
            const float* cp = g_cnf + (size_t)kk * DIM;
            const float* xr = x + (size_t)(row0 + row) * DIM;
            double d0 = 0, d1 = 0, d2 = 0, d3 = 0;
            #pragma unroll
            for (int j = 0; j < DIM; j += 4) {
                d0 += (double)(xr[j]     / rn) * (double)cp[j];
                d1 += (double)(xr[j + 1] / rn) * (double)cp[j + 1];
                d2 += (double)(xr[j + 2] / rn) * (double)cp[j + 2];
                d3 += (double)(xr[j + 3] / rn) * (double)cp[j + 3];
            }
            sc = ((d0 + d1) + (d2 + d3)) - g_biasd[kk];
        }
        #pragma unroll
        for (int off = 1; off <= 8; off <<= 1) {
            double os = __shfl_xor_sync(0xffffffffu, sc, off);
            int    oi = __shfl_xor_sync(0xffffffffu, kk, off);
            if (os > sc || (os == sc && oi < kk)) { sc = os; kk = oi; }
        }
        if (lane == 0) isw[row] = kk;
    }
    __syncthreads();

    // ---- outputs: STE quantized + indices + partial SSE ----
    const float4* xg4 = (const float4*)(x + (size_t)row0 * DIM);
    float4*       og4 = (float4*)(out + (size_t)row0 * DIM);
    float sse = 0.f;
    #pragma unroll
    for (int i = 0; i < 16; i++) {
        int e4 = tid + i * 256;                // 0..4095
        int r = e4 >> 4, c4 = e4 & 15;
        int k = isw[r];
        float4 xv = xg4[e4];
        float4 q  = *(const float4*)(cb + (size_t)k * DIM + c4 * 4);
        float4 o;
        float d;
        d = q.x - xv.x; sse += d * d; o.x = xv.x + d;
        d = q.y - xv.y; sse += d * d; o.y = xv.y + d;
        d = q.z - xv.z; sse += d * d; o.z = xv.z + d;
        d = q.w - xv.w; sse += d * d; o.w = xv.w + d;
        og4[e4] = o;
    }
    if (tid < MTILE) out[(size_t)NQ + 2 + row0 + tid] = (float)isw[tid];

    #pragma unroll
    for (int o = 16; o > 0; o >>= 1) sse += __shfl_xor_sync(0xffffffffu, sse, o);
    if (lane == 0) red[wid] = sse;
    __syncthreads();
    if (tid == 0) {
        float t = 0.f;
        #pragma unroll
        for (int w = 0; w < 8; w++) t += red[w];
        g_partials[blockIdx.x] = t;
    }
}

// ============================================================================
// Kernel 3: reduce partials -> both losses
// ============================================================================
__global__ void vq_fin(float* __restrict__ out) {
    __shared__ float red[8];
    int tid = threadIdx.x;
    float s = 0.f;
    #pragma unroll
    for (int i = 0; i < 4; i++) s += g_partials[tid + i * 256];
    #pragma unroll
    for (int o = 16; o > 0; o >>= 1) s += __shfl_xor_sync(0xffffffffu, s, o);
    if ((tid & 31) == 0) red[tid >> 5] = s;
    __syncthreads();
    if (tid == 0) {
        float t = 0.f;
        #pragma unroll
        for (int w = 0; w < 8; w++) t += red[w];
        float loss = t / 16777216.0f;
        out[NQ]     = loss;   // codebook_loss
        out[NQ + 1] = loss;   // commitment_loss
    }
}

// ============================================================================
extern "C" void kernel_launch(void* const* d_in, const int* in_sizes, int n_in,
                              void* d_out, int out_size) {
    const float* x;
    const float* cb;
    if (in_sizes[0] == NROWS * DIM) {
        x  = (const float*)d_in[0];
        cb = (const float*)d_in[1];
    } else {
        x  = (const float*)d_in[1];
        cb = (const float*)d_in[0];
    }
    float* out = (float*)d_out;

    cudaFuncSetAttribute(vq_main, cudaFuncAttributeMaxDynamicSharedMemorySize, SM_TOTAL);

    vq_prep<<<128, 256>>>(cb);
    vq_main<<<NCTAS, 256, SM_TOTAL>>>(x, cb, out);
    vq_fin<<<1, 256>>>(out);
}

// round 8
// speedup vs baseline: 1.6965x; 1.6965x over previous
#include <cuda_runtime.h>
#include <cuda_fp16.h>
#include <cstdint>
#include <math.h>

// ============================================================================
// VectorQuantizer — base-target ISA (mma.sync m16n8k16 + ldmatrix + cp.async)
//   N = 262144 rows, D = 64, K = 1024 codes.
//   key_k = dot(xn, cn_k) - 0.5*||cn_k||^2   (argmax == reference argmin)
//   fp16 HMMA scores, branch-free packed-key top-3, fp64 rescue of tight rows.
// ============================================================================

#define NROWS   262144
#define DIM     64
#define KCODES  1024
#define NQ      16777216
#define TILES   2048
#define THRESH  2e-3f

// ---- device scratch ----
__device__ __align__(16) __half  g_bh[KCODES * DIM];   // normalized codebook fp16
__device__ __align__(16) float   g_cnf[KCODES * DIM];  // normalized codebook fp32
__device__ double                g_biasd[KCODES];      // 0.5*||cn||^2 fp64
__device__ float                 g_biasf[KCODES];      // 0.5*||cn||^2 fp32
__device__ float                 g_partials[TILES];

// ---- smem layout (bytes) ----
#define SM_XS    0          // 128 x 68 floats           = 34816
#define SM_A     34816      // 128 x 72 halfs (144B)     = 18432
#define SM_B     53248      // 2 x 128 x 144B            = 36864
#define SM_BIAS  90112      // 1024 floats (2 - bias)    = 4096
#define SM_RN    94208      // 128 floats                = 512
#define SM_CAND  94720      // 128 x 12 uint16           = 3072
#define SM_LIST  97792      // 128 ints                  = 512
#define SM_CNT   98304      // 16
#define SM_ISW   98320      // 128 ints                  = 512
#define SM_RED   98832      // 32
#define SM_TOTAL 98864

// ---- PTX helpers ----
__device__ __forceinline__ void mma16816(float c[4], const uint32_t a[4],
                                         uint32_t b0, uint32_t b1) {
    asm volatile(
        "mma.sync.aligned.m16n8k16.row.col.f32.f16.f16.f32 "
        "{%0,%1,%2,%3}, {%4,%5,%6,%7}, {%8,%9}, {%0,%1,%2,%3};"
        : "+f"(c[0]), "+f"(c[1]), "+f"(c[2]), "+f"(c[3])
        : "r"(a[0]), "r"(a[1]), "r"(a[2]), "r"(a[3]), "r"(b0), "r"(b1));
}
__device__ __forceinline__ void ldm4(uint32_t addr, uint32_t& r0, uint32_t& r1,
                                     uint32_t& r2, uint32_t& r3) {
    asm volatile("ldmatrix.sync.aligned.m8n8.x4.shared.b16 {%0,%1,%2,%3}, [%4];"
                 : "=r"(r0), "=r"(r1), "=r"(r2), "=r"(r3) : "r"(addr));
}
__device__ __forceinline__ uint32_t smem_u32(const void* p) {
    uint32_t a;
    asm("{ .reg .u64 t; cvta.to.shared.u64 t, %1; cvt.u32.u64 %0, t; }"
        : "=r"(a) : "l"(p));
    return a;
}
__device__ __forceinline__ void cp16(uint32_t dst, const void* src) {
    asm volatile("cp.async.cg.shared.global [%0], [%1], 16;"
                 :: "r"(dst), "l"(src) : "memory");
}
__device__ __forceinline__ void cp_commit() {
    asm volatile("cp.async.commit_group;" ::: "memory");
}
__device__ __forceinline__ void cp_wait1() {
    asm volatile("cp.async.wait_group 1;" ::: "memory");
}
__device__ __forceinline__ void cp_wait0() {
    asm volatile("cp.async.wait_group 0;" ::: "memory");
}

// packed key: upper 22 bits = biased score, low 10 bits = (1023 - col)
__device__ __forceinline__ uint32_t pkkey(float s, uint32_t invk) {
    return (__float_as_uint(s) & 0xFFFFFC00u) | invk;
}
// branch-free sorted top-3 insert: K0 >= K1 >= K2 (5 min/max ops)
__device__ __forceinline__ void ins3u(uint32_t K[3], uint32_t s) {
    uint32_t lo  = umin(s, K[0]);  K[0] = umax(s, K[0]);
    uint32_t lo2 = umin(lo, K[1]); K[1] = umax(lo, K[1]);
    K[2] = umax(lo2, K[2]);
}

// ============================================================================
// Kernel 1: codebook prep — warp per code
// ============================================================================
__global__ void vq_prep(const float* __restrict__ cb) {
    int wid  = threadIdx.x >> 5;
    int lane = threadIdx.x & 31;
    int k = blockIdx.x * 8 + wid;
    float2 v = ((const float2*)(cb + (size_t)k * DIM))[lane];
    float s = v.x * v.x + v.y * v.y;
    #pragma unroll
    for (int o = 16; o > 0; o >>= 1) s += __shfl_xor_sync(0xffffffffu, s, o);
    float n = fmaxf(sqrtf(s), 1e-12f);
    float a0 = v.x / n, a1 = v.y / n;
    ((float2*)(g_cnf + (size_t)k * DIM))[lane] = make_float2(a0, a1);
    ((__half2*)(g_bh + (size_t)k * DIM))[lane] =
        __halves2half2(__float2half_rn(a0), __float2half_rn(a1));
    double bd = (double)a0 * (double)a0 + (double)a1 * (double)a1;
    #pragma unroll
    for (int o = 16; o > 0; o >>= 1) bd += __shfl_xor_sync(0xffffffffu, bd, o);
    if (lane == 0) {
        g_biasd[k] = 0.5 * bd;
        g_biasf[k] = (float)(0.5 * bd);
    }
}

// ============================================================================
// Kernel 2: GEMM + argmax + rescue + outputs.  128 rows/CTA, 8 warps x m16.
// ============================================================================
__global__ void __launch_bounds__(256, 2)
vq_main(const float* __restrict__ x, const float* __restrict__ cb,
        float* __restrict__ out) {
    extern __shared__ char smem[];
    const uint32_t sb = smem_u32(smem);
    const int tid  = threadIdx.x;
    const int wid  = tid >> 5;
    const int lane = tid & 31;
    const int row0 = blockIdx.x * 128;

    float*    xs   = (float*)(smem + SM_XS);     // stride 68 floats
    float*    bsm  = (float*)(smem + SM_BIAS);   // 2.0f - bias
    float*    rnsm = (float*)(smem + SM_RN);
    uint16_t* cand = (uint16_t*)(smem + SM_CAND);
    int*      list = (int*)(smem + SM_LIST);
    int*      cnt  = (int*)(smem + SM_CNT);
    int*      isw  = (int*)(smem + SM_ISW);
    float*    red  = (float*)(smem + SM_RED);

    if (tid == 0) *cnt = 0;

    // ---- stage x tile ----
    {
        const float4* x4 = (const float4*)(x + (size_t)row0 * DIM);
        #pragma unroll
        for (int i = 0; i < 8; i++) {
            int g0 = tid + i * 256;           // 2048 float4
            float4 v = x4[g0];
            int r = g0 >> 4, c4 = g0 & 15;
            float* d = xs + r * 68 + c4 * 4;
            d[0] = v.x; d[1] = v.y; d[2] = v.z; d[3] = v.w;
        }
        #pragma unroll
        for (int i = 0; i < 4; i++) {
            int g0 = tid + i * 256;
            bsm[g0] = 2.0f - g_biasf[g0];
        }
    }

    // ---- prefetch B chunks 0,1 via cp.async ----
    const __half* bh = g_bh;
    #pragma unroll
    for (int pc = 0; pc < 2; pc++) {
        #pragma unroll
        for (int i = 0; i < 4; i++) {
            int idx = tid + i * 256;          // 0..1023
            int r = idx >> 3, seg = idx & 7;
            cp16(sb + SM_B + pc * 18432 + r * 144 + seg * 16,
                 bh + ((size_t)(pc * 128 + r)) * DIM + seg * 8);
        }
        cp_commit();
    }
    __syncthreads();

    // ---- normalize rows -> fp16 A ----
    if (tid < 128) {
        int r = tid;
        float s = 0.f;
        #pragma unroll
        for (int j = 0; j < DIM; j++) { float v = xs[r * 68 + j]; s += v * v; }
        float n = fmaxf(sqrtf(s), 1e-12f);
        rnsm[r] = n;
        __half2* arow = (__half2*)(smem + SM_A + r * 144);
        #pragma unroll
        for (int j2 = 0; j2 < 32; j2++) {
            float a0 = xs[r * 68 + 2 * j2]     / n;
            float a1 = xs[r * 68 + 2 * j2 + 1] / n;
            arow[j2] = __halves2half2(__float2half_rn(a0), __float2half_rn(a1));
        }
    }
    __syncthreads();

    // ---- A fragments via ldmatrix (persist in registers) ----
    const int lr = lane & 7, m = lane >> 3;
    const int Rb = wid * 16;
    const uint32_t a_loff = (uint32_t)((lr + (m & 1) * 8) * 144 + (m >> 1) * 16);
    const uint32_t b_loff = (uint32_t)(((m >> 1) * 8 + lr) * 144 + (m & 1) * 16);
    uint32_t afr[4][4];
    #pragma unroll
    for (int ks = 0; ks < 4; ks++)
        ldm4(sb + SM_A + (uint32_t)(Rb * 144 + ks * 32) + a_loff,
             afr[ks][0], afr[ks][1], afr[ks][2], afr[ks][3]);

    // ---- main loop: 8 chunks of 128 codes, double-buffered ----
    uint32_t K0[3] = {0, 0, 0}, K1[3] = {0, 0, 0};
    const int c = lane & 3;

    #pragma unroll 1
    for (int ch = 0; ch < 8; ch++) {
        if (ch == 7) cp_wait0(); else cp_wait1();
        __syncthreads();
        const uint32_t Bb = sb + SM_B + (uint32_t)((ch & 1) * 18432) + b_loff;
        const int cb0 = ch * 128 + 2 * c;

        #pragma unroll
        for (int nbp = 0; nbp < 8; nbp++) {
            uint32_t bk[4][4];
            #pragma unroll
            for (int ks = 0; ks < 4; ks++)
                ldm4(Bb + (uint32_t)(nbp * 2304 + ks * 32),
                     bk[ks][0], bk[ks][1], bk[ks][2], bk[ks][3]);
            float acc0[4] = {0.f, 0.f, 0.f, 0.f};
            float acc1[4] = {0.f, 0.f, 0.f, 0.f};
            #pragma unroll
            for (int ks = 0; ks < 4; ks++) {
                mma16816(acc0, afr[ks], bk[ks][0], bk[ks][1]);
                mma16816(acc1, afr[ks], bk[ks][2], bk[ks][3]);
            }
            // branch-free epilogue: biased score -> packed key -> top-3
            int col0 = cb0 + nbp * 16;
            uint32_t inv = (uint32_t)(1023 - col0);
            float2 bb0 = *(const float2*)(bsm + col0);
            float2 bb1 = *(const float2*)(bsm + col0 + 8);
            ins3u(K0, pkkey(acc0[0] + bb0.x, inv));
            ins3u(K0, pkkey(acc0[1] + bb0.y, inv - 1));
            ins3u(K0, pkkey(acc1[0] + bb1.x, inv - 8));
            ins3u(K0, pkkey(acc1[1] + bb1.y, inv - 9));
            ins3u(K1, pkkey(acc0[2] + bb0.x, inv));
            ins3u(K1, pkkey(acc0[3] + bb0.y, inv - 1));
            ins3u(K1, pkkey(acc1[2] + bb1.x, inv - 8));
            ins3u(K1, pkkey(acc1[3] + bb1.y, inv - 9));
        }
        __syncthreads();
        if (ch < 6) {                          // prefetch chunk ch+2
            int pc = ch + 2;
            #pragma unroll
            for (int i = 0; i < 4; i++) {
                int idx = tid + i * 256;
                int r = idx >> 3, seg = idx & 7;
                cp16(sb + SM_B + (pc & 1) * 18432 + r * 144 + seg * 16,
                     bh + ((size_t)(pc * 128 + r)) * DIM + seg * 8);
            }
            cp_commit();
        }
    }

    // ---- quad merge: row best / margin / candidate dump ----
    const int g = lane >> 2;
    #pragma unroll
    for (int h = 0; h < 2; h++) {
        uint32_t* K = h ? K1 : K0;
        int row = Rb + 8 * h + g;
        uint32_t bs = K[0];
        bs = umax(bs, __shfl_xor_sync(0xffffffffu, bs, 1));
        bs = umax(bs, __shfl_xor_sync(0xffffffffu, bs, 2));
        uint32_t sc = (K[0] == bs) ? K[1] : K[0];
        sc = umax(sc, __shfl_xor_sync(0xffffffffu, sc, 1));
        sc = umax(sc, __shfl_xor_sync(0xffffffffu, sc, 2));
        #pragma unroll
        for (int j = 0; j < 3; j++)
            cand[row * 12 + 3 * c + j] = (uint16_t)(1023u - (K[j] & 1023u));
        if (c == 0) {
            isw[row] = (int)(1023u - (bs & 1023u));
            float mf = __uint_as_float(bs & 0xFFFFFC00u)
                     - __uint_as_float(sc & 0xFFFFFC00u);
            if (mf < THRESH) { int p = atomicAdd(cnt, 1); list[p] = row; }
        }
    }
    __syncthreads();

    // ---- fp64 rescue of tight rows (12 candidates each, warp per row) ----
    int nflag = *cnt;
    for (int e = wid; e < nflag; e += 8) {
        int row = list[e];
        double scv = -1e300; int kk = 0x7fffffff;
        if (lane < 12) {
            kk = (int)cand[row * 12 + lane];
            float rn = rnsm[row];
            const float* cp = g_cnf + (size_t)kk * DIM;
            const float* xr = xs + row * 68;
            double d0 = 0, d1 = 0, d2 = 0, d3 = 0;
            #pragma unroll
            for (int j = 0; j < DIM; j += 4) {
                d0 += (double)(xr[j]     / rn) * (double)cp[j];
                d1 += (double)(xr[j + 1] / rn) * (double)cp[j + 1];
                d2 += (double)(xr[j + 2] / rn) * (double)cp[j + 2];
                d3 += (double)(xr[j + 3] / rn) * (double)cp[j + 3];
            }
            scv = ((d0 + d1) + (d2 + d3)) - g_biasd[kk];
        }
        #pragma unroll
        for (int off = 1; off <= 8; off <<= 1) {
            double os = __shfl_xor_sync(0xffffffffu, scv, off);
            int    oi = __shfl_xor_sync(0xffffffffu, kk, off);
            if (os > scv || (os == scv && oi < kk)) { scv = os; kk = oi; }
        }
        if (lane == 0) isw[row] = kk;
    }
    __syncthreads();

    // ---- outputs: STE quantized + indices + partial SSE ----
    float4* og4 = (float4*)(out + (size_t)row0 * DIM);
    float sse = 0.f;
    #pragma unroll
    for (int i = 0; i < 8; i++) {
        int e4 = tid + i * 256;                // 0..2047 float4
        int r = e4 >> 4, c4 = e4 & 15;
        int k = isw[r];
        const float* xr = xs + r * 68 + c4 * 4;
        float4 q  = *(const float4*)(cb + (size_t)k * DIM + c4 * 4);
        float4 o; float d;
        d = q.x - xr[0]; sse += d * d; o.x = xr[0] + d;
        d = q.y - xr[1]; sse += d * d; o.y = xr[1] + d;
        d = q.z - xr[2]; sse += d * d; o.z = xr[2] + d;
        d = q.w - xr[3]; sse += d * d; o.w = xr[3] + d;
        og4[e4] = o;
    }
    if (tid < 128) out[(size_t)NQ + 2 + row0 + tid] = (float)isw[tid];

    #pragma unroll
    for (int o = 16; o > 0; o >>= 1) sse += __shfl_xor_sync(0xffffffffu, sse, o);
    if (lane == 0) red[wid] = sse;
    __syncthreads();
    if (tid == 0) {
        float t = 0.f;
        #pragma unroll
        for (int w = 0; w < 8; w++) t += red[w];
        g_partials[blockIdx.x] = t;
    }
}

// ============================================================================
// Kernel 3: reduce partials -> both losses
// ============================================================================
__global__ void vq_fin(float* __restrict__ out) {
    __shared__ float red[8];
    int tid = threadIdx.x;
    float s = 0.f;
    #pragma unroll
    for (int i = 0; i < 8; i++) s += g_partials[tid + i * 256];
    #pragma unroll
    for (int o = 16; o > 0; o >>= 1) s += __shfl_xor_sync(0xffffffffu, s, o);
    if ((tid & 31) == 0) red[tid >> 5] = s;
    __syncthreads();
    if (tid == 0) {
        float t = 0.f;
        #pragma unroll
        for (int w = 0; w < 8; w++) t += red[w];
        float loss = t / 16777216.0f;
        out[NQ]     = loss;   // codebook_loss
        out[NQ + 1] = loss;   // commitment_loss
    }
}

// ============================================================================
extern "C" void kernel_launch(void* const* d_in, const int* in_sizes, int n_in,
                              void* d_out, int out_size) {
    const float* x;
    const float* cb;
    if (in_sizes[0] == NROWS * DIM) {
        x  = (const float*)d_in[0];
        cb = (const float*)d_in[1];
    } else {
        x  = (const float*)d_in[1];
        cb = (const float*)d_in[0];
    }
    float* out = (float*)d_out;

    cudaFuncSetAttribute(vq_main, cudaFuncAttributeMaxDynamicSharedMemorySize, SM_TOTAL);

    vq_prep<<<128, 256>>>(cb);
    vq_main<<<TILES, 256, SM_TOTAL>>>(x, cb, out);
    vq_fin<<<1, 256>>>(out);
}

// round 9
// speedup vs baseline: 1.7616x; 1.0383x over previous
#include <cuda_runtime.h>
#include <cuda_fp16.h>
#include <cstdint>
#include <math.h>

// ============================================================================
// VectorQuantizer — base-target ISA (mma.sync m16n8k16 + ldmatrix + cp.async)
//   N = 262144 rows, D = 64, K = 1024 codes.
//   key_k = dot(xn, cn_k) - 0.5*||cn_k||^2   (argmax == reference argmin)
//   fp16 HMMA scores, branch-free packed-key top-3, fp64 rescue of tight rows.
//   R9: no fp32 x staging -> 64KB smem -> 3 CTAs/SM (24 warps) for latency hiding.
// ============================================================================

#define NROWS   262144
#define DIM     64
#define KCODES  1024
#define NQ      16777216
#define TILES   2048
#define THRESH  2e-3f

// ---- device scratch ----
__device__ __align__(16) __half  g_bh[KCODES * DIM];   // normalized codebook fp16
__device__ __align__(16) float   g_cnf[KCODES * DIM];  // normalized codebook fp32
__device__ double                g_biasd[KCODES];      // 0.5*||cn||^2 fp64
__device__ float                 g_biasf[KCODES];      // 0.5*||cn||^2 fp32
__device__ float                 g_partials[TILES];

// ---- smem layout (bytes) ----
#define SM_B     0          // 2 x (128 codes x 144B)    = 36864
#define SM_A     36864      // 128 rows x 144B           = 18432
#define SM_BIAS  55296      // 1024 floats (2 - bias)    = 4096
#define SM_RN    59392      // 128 floats                = 512
#define SM_CAND  59904      // 128 x 12 uint16           = 3072
#define SM_LIST  62976      // 128 ints                  = 512
#define SM_CNT   63488      // 16
#define SM_ISW   63504      // 128 ints                  = 512
#define SM_RED   64016      // 32
#define SM_TOTAL 64048

// ---- PTX helpers ----
__device__ __forceinline__ void mma16816(float c[4], const uint32_t a[4],
                                         uint32_t b0, uint32_t b1) {
    asm volatile(
        "mma.sync.aligned.m16n8k16.row.col.f32.f16.f16.f32 "
        "{%0,%1,%2,%3}, {%4,%5,%6,%7}, {%8,%9}, {%0,%1,%2,%3};"
        : "+f"(c[0]), "+f"(c[1]), "+f"(c[2]), "+f"(c[3])
        : "r"(a[0]), "r"(a[1]), "r"(a[2]), "r"(a[3]), "r"(b0), "r"(b1));
}
__device__ __forceinline__ void ldm4(uint32_t addr, uint32_t& r0, uint32_t& r1,
                                     uint32_t& r2, uint32_t& r3) {
    asm volatile("ldmatrix.sync.aligned.m8n8.x4.shared.b16 {%0,%1,%2,%3}, [%4];"
                 : "=r"(r0), "=r"(r1), "=r"(r2), "=r"(r3) : "r"(addr));
}
__device__ __forceinline__ uint32_t smem_u32(const void* p) {
    uint32_t a;
    asm("{ .reg .u64 t; cvta.to.shared.u64 t, %1; cvt.u32.u64 %0, t; }"
        : "=r"(a) : "l"(p));
    return a;
}
__device__ __forceinline__ void cp16(uint32_t dst, const void* src) {
    asm volatile("cp.async.cg.shared.global [%0], [%1], 16;"
                 :: "r"(dst), "l"(src) : "memory");
}
__device__ __forceinline__ void cp_commit() {
    asm volatile("cp.async.commit_group;" ::: "memory");
}
__device__ __forceinline__ void cp_wait1() {
    asm volatile("cp.async.wait_group 1;" ::: "memory");
}
__device__ __forceinline__ void cp_wait0() {
    asm volatile("cp.async.wait_group 0;" ::: "memory");
}

// packed key: upper 22 bits = biased score, low 10 bits = (1023 - col)
__device__ __forceinline__ uint32_t pkkey(float s, uint32_t invk) {
    return (__float_as_uint(s) & 0xFFFFFC00u) | invk;
}
// branch-free sorted top-3 insert: K0 >= K1 >= K2 (5 min/max ops)
__device__ __forceinline__ void ins3u(uint32_t K[3], uint32_t s) {
    uint32_t lo  = umin(s, K[0]);  K[0] = umax(s, K[0]);
    uint32_t lo2 = umin(lo, K[1]); K[1] = umax(lo, K[1]);
    K[2] = umax(lo2, K[2]);
}

// ============================================================================
// Kernel 1: codebook prep — warp per code
// ============================================================================
__global__ void vq_prep(const float* __restrict__ cb) {
    int wid  = threadIdx.x >> 5;
    int lane = threadIdx.x & 31;
    int k = blockIdx.x * 8 + wid;
    float2 v = ((const float2*)(cb + (size_t)k * DIM))[lane];
    float s = v.x * v.x + v.y * v.y;
    #pragma unroll
    for (int o = 16; o > 0; o >>= 1) s += __shfl_xor_sync(0xffffffffu, s, o);
    float n = fmaxf(sqrtf(s), 1e-12f);
    float a0 = v.x / n, a1 = v.y / n;
    ((float2*)(g_cnf + (size_t)k * DIM))[lane] = make_float2(a0, a1);
    ((__half2*)(g_bh + (size_t)k * DIM))[lane] =
        __halves2half2(__float2half_rn(a0), __float2half_rn(a1));
    double bd = (double)a0 * (double)a0 + (double)a1 * (double)a1;
    #pragma unroll
    for (int o = 16; o > 0; o >>= 1) bd += __shfl_xor_sync(0xffffffffu, bd, o);
    if (lane == 0) {
        g_biasd[k] = 0.5 * bd;
        g_biasf[k] = (float)(0.5 * bd);
    }
}

// ============================================================================
// Kernel 2: GEMM + argmax + rescue + outputs.  128 rows/CTA, 8 warps x m16.
// ============================================================================
__global__ void __launch_bounds__(256, 3)
vq_main(const float* __restrict__ x, const float* __restrict__ cb,
        float* __restrict__ out) {
    extern __shared__ char smem[];
    const uint32_t sb = smem_u32(smem);
    const int tid  = threadIdx.x;
    const int wid  = tid >> 5;
    const int lane = tid & 31;
    const int row0 = blockIdx.x * 128;

    float*    bsm  = (float*)(smem + SM_BIAS);   // 2.0f - bias
    float*    rnsm = (float*)(smem + SM_RN);
    uint16_t* cand = (uint16_t*)(smem + SM_CAND);
    int*      list = (int*)(smem + SM_LIST);
    int*      cnt  = (int*)(smem + SM_CNT);
    int*      isw  = (int*)(smem + SM_ISW);
    float*    red  = (float*)(smem + SM_RED);

    if (tid == 0) *cnt = 0;

    // ---- prefetch B chunks 0,1 via cp.async ----
    const __half* bh = g_bh;
    #pragma unroll
    for (int pc = 0; pc < 2; pc++) {
        #pragma unroll
        for (int i = 0; i < 4; i++) {
            int idx = tid + i * 256;          // 0..1023
            int r = idx >> 3, seg = idx & 7;
            cp16(sb + SM_B + pc * 18432 + r * 144 + seg * 16,
                 bh + ((size_t)(pc * 128 + r)) * DIM + seg * 8);
        }
        cp_commit();
    }

    // ---- bias to smem ----
    #pragma unroll
    for (int i = 0; i < 4; i++) {
        int g0 = tid + i * 256;
        bsm[g0] = 2.0f - g_biasf[g0];
    }

    // ---- normalize rows -> fp16 A (warp per row, gmem-direct) ----
    {
        const float2* x2 = (const float2*)(x + (size_t)row0 * DIM);
        #pragma unroll 4
        for (int j = 0; j < 16; j++) {
            int r = wid + 8 * j;              // 0..127
            float2 v = x2[r * 32 + lane];
            float s = v.x * v.x + v.y * v.y;
            #pragma unroll
            for (int o = 16; o > 0; o >>= 1)
                s += __shfl_xor_sync(0xffffffffu, s, o);
            float n = fmaxf(sqrtf(s), 1e-12f);
            if (lane == 0) rnsm[r] = n;
            *(__half2*)(smem + SM_A + r * 144 + lane * 4) =
                __halves2half2(__float2half_rn(v.x / n), __float2half_rn(v.y / n));
        }
    }
    __syncthreads();

    // ---- A fragments via ldmatrix (persist in registers) ----
    const int lr = lane & 7, m = lane >> 3;
    const int Rb = wid * 16;
    const uint32_t a_loff = (uint32_t)((lr + (m & 1) * 8) * 144 + (m >> 1) * 16);
    const uint32_t b_loff = (uint32_t)(((m >> 1) * 8 + lr) * 144 + (m & 1) * 16);
    uint32_t afr[4][4];
    #pragma unroll
    for (int ks = 0; ks < 4; ks++)
        ldm4(sb + SM_A + (uint32_t)(Rb * 144 + ks * 32) + a_loff,
             afr[ks][0], afr[ks][1], afr[ks][2], afr[ks][3]);

    // ---- main loop: 8 chunks of 128 codes, double-buffered ----
    uint32_t K0[3] = {0, 0, 0}, K1[3] = {0, 0, 0};
    const int c = lane & 3;

    #pragma unroll 1
    for (int ch = 0; ch < 8; ch++) {
        if (ch == 7) cp_wait0(); else cp_wait1();
        __syncthreads();
        const uint32_t Bb = sb + SM_B + (uint32_t)((ch & 1) * 18432) + b_loff;
        const int cb0 = ch * 128 + 2 * c;

        #pragma unroll
        for (int nbp = 0; nbp < 8; nbp++) {
            uint32_t bk[4][4];
            #pragma unroll
            for (int ks = 0; ks < 4; ks++)
                ldm4(Bb + (uint32_t)(nbp * 2304 + ks * 32),
                     bk[ks][0], bk[ks][1], bk[ks][2], bk[ks][3]);
            float acc0[4] = {0.f, 0.f, 0.f, 0.f};
            float acc1[4] = {0.f, 0.f, 0.f, 0.f};
            #pragma unroll
            for (int ks = 0; ks < 4; ks++) {
                mma16816(acc0, afr[ks], bk[ks][0], bk[ks][1]);
                mma16816(acc1, afr[ks], bk[ks][2], bk[ks][3]);
            }
            // branch-free epilogue: biased score -> packed key -> top-3
            int col0 = cb0 + nbp * 16;
            uint32_t inv = (uint32_t)(1023 - col0);
            float2 bb0 = *(const float2*)(bsm + col0);
            float2 bb1 = *(const float2*)(bsm + col0 + 8);
            ins3u(K0, pkkey(acc0[0] + bb0.x, inv));
            ins3u(K0, pkkey(acc0[1] + bb0.y, inv - 1));
            ins3u(K0, pkkey(acc1[0] + bb1.x, inv - 8));
            ins3u(K0, pkkey(acc1[1] + bb1.y, inv - 9));
            ins3u(K1, pkkey(acc0[2] + bb0.x, inv));
            ins3u(K1, pkkey(acc0[3] + bb0.y, inv - 1));
            ins3u(K1, pkkey(acc1[2] + bb1.x, inv - 8));
            ins3u(K1, pkkey(acc1[3] + bb1.y, inv - 9));
        }
        __syncthreads();
        if (ch < 6) {                          // prefetch chunk ch+2
            int pc = ch + 2;
            #pragma unroll
            for (int i = 0; i < 4; i++) {
                int idx = tid + i * 256;
                int r = idx >> 3, seg = idx & 7;
                cp16(sb + SM_B + (pc & 1) * 18432 + r * 144 + seg * 16,
                     bh + ((size_t)(pc * 128 + r)) * DIM + seg * 8);
            }
            cp_commit();
        }
    }

    // ---- quad merge: row best / margin / candidate dump ----
    const int g = lane >> 2;
    #pragma unroll
    for (int h = 0; h < 2; h++) {
        uint32_t* K = h ? K1 : K0;
        int row = Rb + 8 * h + g;
        uint32_t bs = K[0];
        bs = umax(bs, __shfl_xor_sync(0xffffffffu, bs, 1));
        bs = umax(bs, __shfl_xor_sync(0xffffffffu, bs, 2));
        uint32_t sc = (K[0] == bs) ? K[1] : K[0];
        sc = umax(sc, __shfl_xor_sync(0xffffffffu, sc, 1));
        sc = umax(sc, __shfl_xor_sync(0xffffffffu, sc, 2));
        #pragma unroll
        for (int j = 0; j < 3; j++)
            cand[row * 12 + 3 * c + j] = (uint16_t)(1023u - (K[j] & 1023u));
        if (c == 0) {
            isw[row] = (int)(1023u - (bs & 1023u));
            float mf = __uint_as_float(bs & 0xFFFFFC00u)
                     - __uint_as_float(sc & 0xFFFFFC00u);
            if (mf < THRESH) { int p = atomicAdd(cnt, 1); list[p] = row; }
        }
    }
    __syncthreads();

    // ---- fp64 rescue of tight rows (12 candidates each, warp per row) ----
    int nflag = *cnt;
    for (int e = wid; e < nflag; e += 8) {
        int row = list[e];
        double scv = -1e300; int kk = 0x7fffffff;
        if (lane < 12) {
            kk = (int)cand[row * 12 + lane];
            float rn = rnsm[row];
            const float* cp = g_cnf + (size_t)kk * DIM;
            const float* xr = x + (size_t)(row0 + row) * DIM;
            double d0 = 0, d1 = 0, d2 = 0, d3 = 0;
            #pragma unroll
            for (int j = 0; j < DIM; j += 4) {
                d0 += (double)(xr[j]     / rn) * (double)cp[j];
                d1 += (double)(xr[j + 1] / rn) * (double)cp[j + 1];
                d2 += (double)(xr[j + 2] / rn) * (double)cp[j + 2];
                d3 += (double)(xr[j + 3] / rn) * (double)cp[j + 3];
            }
            scv = ((d0 + d1) + (d2 + d3)) - g_biasd[kk];
        }
        #pragma unroll
        for (int off = 1; off <= 8; off <<= 1) {
            double os = __shfl_xor_sync(0xffffffffu, scv, off);
            int    oi = __shfl_xor_sync(0xffffffffu, kk, off);
            if (os > scv || (os == scv && oi < kk)) { scv = os; kk = oi; }
        }
        if (lane == 0) isw[row] = kk;
    }
    __syncthreads();

    // ---- outputs: STE quantized + indices + partial SSE ----
    const float4* xg4 = (const float4*)(x + (size_t)row0 * DIM);
    float4*       og4 = (float4*)(out + (size_t)row0 * DIM);
    float sse = 0.f;
    #pragma unroll
    for (int i = 0; i < 8; i++) {
        int e4 = tid + i * 256;                // 0..2047 float4
        int r = e4 >> 4, c4 = e4 & 15;
        int k = isw[r];
        float4 xv = xg4[e4];
        float4 q  = *(const float4*)(cb + (size_t)k * DIM + c4 * 4);
        float4 o; float d;
        d = q.x - xv.x; sse += d * d; o.x = xv.x + d;
        d = q.y - xv.y; sse += d * d; o.y = xv.y + d;
        d = q.z - xv.z; sse += d * d; o.z = xv.z + d;
        d = q.w - xv.w; sse += d * d; o.w = xv.w + d;
        og4[e4] = o;
    }
    if (tid < 128) out[(size_t)NQ + 2 + row0 + tid] = (float)isw[tid];

    #pragma unroll
    for (int o = 16; o > 0; o >>= 1) sse += __shfl_xor_sync(0xffffffffu, sse, o);
    if (lane == 0) red[wid] = sse;
    __syncthreads();
    if (tid == 0) {
        float t = 0.f;
        #pragma unroll
        for (int w = 0; w < 8; w++) t += red[w];
        g_partials[blockIdx.x] = t;
    }
}

// ============================================================================
// Kernel 3: reduce partials -> both losses
// ============================================================================
__global__ void vq_fin(float* __restrict__ out) {
    __shared__ float red[8];
    int tid = threadIdx.x;
    float s = 0.f;
    #pragma unroll
    for (int i = 0; i < 8; i++) s += g_partials[tid + i * 256];
    #pragma unroll
    for (int o = 16; o > 0; o >>= 1) s += __shfl_xor_sync(0xffffffffu, s, o);
    if ((tid & 31) == 0) red[tid >> 5] = s;
    __syncthreads();
    if (tid == 0) {
        float t = 0.f;
        #pragma unroll
        for (int w = 0; w < 8; w++) t += red[w];
        float loss = t / 16777216.0f;
        out[NQ]     = loss;   // codebook_loss
        out[NQ + 1] = loss;   // commitment_loss
    }
}

// ============================================================================
extern "C" void kernel_launch(void* const* d_in, const int* in_sizes, int n_in,
                              void* d_out, int out_size) {
    const float* x;
    const float* cb;
    if (in_sizes[0] == NROWS * DIM) {
        x  = (const float*)d_in[0];
        cb = (const float*)d_in[1];
    } else {
        x  = (const float*)d_in[1];
        cb = (const float*)d_in[0];
    }
    float* out = (float*)d_out;

    cudaFuncSetAttribute(vq_main, cudaFuncAttributeMaxDynamicSharedMemorySize, SM_TOTAL);

    vq_prep<<<128, 256>>>(cb);
    vq_main<<<TILES, 256, SM_TOTAL>>>(x, cb, out);
    vq_fin<<<1, 256>>>(out);
}

// round 10
// speedup vs baseline: 1.7989x; 1.0212x over previous
#include <cuda_runtime.h>
#include <cuda_fp16.h>
#include <cstdint>
#include <math.h>

// ============================================================================
// VectorQuantizer — base-target ISA (mma.sync m16n8k16 + ldmatrix + cp.async)
//   N = 262144 rows, D = 64, K = 1024 codes.
//   key_k = dot(xn, cn_k) - 0.5*||cn_k||^2   (argmax == reference argmin)
//   fp16 HMMA scores (bias pre-loaded into MMA accumulator), branch-free
//   packed-key top-2 per lane, fp64 rescue of tight-margin rows.
// ============================================================================

#define NROWS   262144
#define DIM     64
#define KCODES  1024
#define NQ      16777216
#define TILES   2048
#define THRESH  2e-3f

// ---- device scratch ----
__device__ __align__(16) __half  g_bh[KCODES * DIM];   // normalized codebook fp16
__device__ __align__(16) float   g_cnf[KCODES * DIM];  // normalized codebook fp32
__device__ double                g_biasd[KCODES];      // 0.5*||cn||^2 fp64
__device__ float                 g_biasf[KCODES];      // 0.5*||cn||^2 fp32
__device__ float                 g_partials[TILES];

// ---- smem layout (bytes) ----
#define SM_B     0          // 2 x (128 codes x 144B)    = 36864
#define SM_A     36864      // 128 rows x 144B           = 18432
#define SM_BIAS  55296      // 1024 floats (2 - bias)    = 4096
#define SM_RN    59392      // 128 floats                = 512
#define SM_CAND  59904      // 128 x 8 uint16            = 2048
#define SM_LIST  61952      // 128 ints                  = 512
#define SM_CNT   62464      // 16
#define SM_ISW   62480      // 128 ints                  = 512
#define SM_RED   62992      // 32
#define SM_TOTAL 63024

// ---- PTX helpers ----
__device__ __forceinline__ void mma16816(float c[4], const uint32_t a[4],
                                         uint32_t b0, uint32_t b1) {
    asm volatile(
        "mma.sync.aligned.m16n8k16.row.col.f32.f16.f16.f32 "
        "{%0,%1,%2,%3}, {%4,%5,%6,%7}, {%8,%9}, {%0,%1,%2,%3};"
        : "+f"(c[0]), "+f"(c[1]), "+f"(c[2]), "+f"(c[3])
        : "r"(a[0]), "r"(a[1]), "r"(a[2]), "r"(a[3]), "r"(b0), "r"(b1));
}
__device__ __forceinline__ void ldm4(uint32_t addr, uint32_t& r0, uint32_t& r1,
                                     uint32_t& r2, uint32_t& r3) {
    asm volatile("ldmatrix.sync.aligned.m8n8.x4.shared.b16 {%0,%1,%2,%3}, [%4];"
                 : "=r"(r0), "=r"(r1), "=r"(r2), "=r"(r3) : "r"(addr));
}
__device__ __forceinline__ uint32_t smem_u32(const void* p) {
    uint32_t a;
    asm("{ .reg .u64 t; cvta.to.shared.u64 t, %1; cvt.u32.u64 %0, t; }"
        : "=r"(a) : "l"(p));
    return a;
}
__device__ __forceinline__ void cp16(uint32_t dst, const void* src) {
    asm volatile("cp.async.cg.shared.global [%0], [%1], 16;"
                 :: "r"(dst), "l"(src) : "memory");
}
__device__ __forceinline__ void cp_commit() {
    asm volatile("cp.async.commit_group;" ::: "memory");
}
__device__ __forceinline__ void cp_wait1() {
    asm volatile("cp.async.wait_group 1;" ::: "memory");
}
__device__ __forceinline__ void cp_wait0() {
    asm volatile("cp.async.wait_group 0;" ::: "memory");
}

// packed key: upper 22 bits = biased score, low 10 bits = (1023 - col)
__device__ __forceinline__ uint32_t pkkey(float s, uint32_t invk) {
    return (__float_as_uint(s) & 0xFFFFFC00u) | invk;   // single LOP3
}
// branch-free sorted top-2 insert: K0 >= K1 (3 min/max ops)
__device__ __forceinline__ void ins2u(uint32_t K[2], uint32_t s) {
    uint32_t lo = umin(s, K[0]);
    K[0] = umax(s, K[0]);
    K[1] = umax(lo, K[1]);
}

// ============================================================================
// Kernel 1: codebook prep — warp per code
// ============================================================================
__global__ void vq_prep(const float* __restrict__ cb) {
    int wid  = threadIdx.x >> 5;
    int lane = threadIdx.x & 31;
    int k = blockIdx.x * 8 + wid;
    float2 v = ((const float2*)(cb + (size_t)k * DIM))[lane];
    float s = v.x * v.x + v.y * v.y;
    #pragma unroll
    for (int o = 16; o > 0; o >>= 1) s += __shfl_xor_sync(0xffffffffu, s, o);
    float n = fmaxf(sqrtf(s), 1e-12f);
    float a0 = v.x / n, a1 = v.y / n;
    ((float2*)(g_cnf + (size_t)k * DIM))[lane] = make_float2(a0, a1);
    ((__half2*)(g_bh + (size_t)k * DIM))[lane] =
        __halves2half2(__float2half_rn(a0), __float2half_rn(a1));
    double bd = (double)a0 * (double)a0 + (double)a1 * (double)a1;
    #pragma unroll
    for (int o = 16; o > 0; o >>= 1) bd += __shfl_xor_sync(0xffffffffu, bd, o);
    if (lane == 0) {
        g_biasd[k] = 0.5 * bd;
        g_biasf[k] = (float)(0.5 * bd);
    }
}

// ============================================================================
// Kernel 2: GEMM + argmax + rescue + outputs.  128 rows/CTA, 8 warps x m16.
// ============================================================================
__global__ void __launch_bounds__(256, 3)
vq_main(const float* __restrict__ x, const float* __restrict__ cb,
        float* __restrict__ out) {
    extern __shared__ char smem[];
    const uint32_t sb = smem_u32(smem);
    const int tid  = threadIdx.x;
    const int wid  = tid >> 5;
    const int lane = tid & 31;
    const int row0 = blockIdx.x * 128;

    float*    bsm  = (float*)(smem + SM_BIAS);   // 2.0f - bias
    float*    rnsm = (float*)(smem + SM_RN);
    uint16_t* cand = (uint16_t*)(smem + SM_CAND);
    int*      list = (int*)(smem + SM_LIST);
    int*      cnt  = (int*)(smem + SM_CNT);
    int*      isw  = (int*)(smem + SM_ISW);
    float*    red  = (float*)(smem + SM_RED);

    if (tid == 0) *cnt = 0;

    // ---- prefetch B chunks 0,1 via cp.async ----
    const __half* bh = g_bh;
    #pragma unroll
    for (int pc = 0; pc < 2; pc++) {
        #pragma unroll
        for (int i = 0; i < 4; i++) {
            int idx = tid + i * 256;          // 0..1023
            int r = idx >> 3, seg = idx & 7;
            cp16(sb + SM_B + pc * 18432 + r * 144 + seg * 16,
                 bh + ((size_t)(pc * 128 + r)) * DIM + seg * 8);
        }
        cp_commit();
    }

    // ---- bias to smem ----
    #pragma unroll
    for (int i = 0; i < 4; i++) {
        int g0 = tid + i * 256;
        bsm[g0] = 2.0f - g_biasf[g0];
    }

    // ---- normalize rows -> fp16 A (warp per row, gmem-direct) ----
    {
        const float2* x2 = (const float2*)(x + (size_t)row0 * DIM);
        #pragma unroll 4
        for (int j = 0; j < 16; j++) {
            int r = wid + 8 * j;              // 0..127
            float2 v = x2[r * 32 + lane];
            float s = v.x * v.x + v.y * v.y;
            #pragma unroll
            for (int o = 16; o > 0; o >>= 1)
                s += __shfl_xor_sync(0xffffffffu, s, o);
            float n = fmaxf(sqrtf(s), 1e-12f);
            if (lane == 0) rnsm[r] = n;
            *(__half2*)(smem + SM_A + r * 144 + lane * 4) =
                __halves2half2(__float2half_rn(v.x / n), __float2half_rn(v.y / n));
        }
    }
    __syncthreads();

    // ---- A fragments via ldmatrix (persist in registers) ----
    const int lr = lane & 7, m = lane >> 3;
    const int Rb = wid * 16;
    const uint32_t a_loff = (uint32_t)((lr + (m & 1) * 8) * 144 + (m >> 1) * 16);
    const uint32_t b_loff = (uint32_t)(((m >> 1) * 8 + lr) * 144 + (m & 1) * 16);
    uint32_t afr[4][4];
    #pragma unroll
    for (int ks = 0; ks < 4; ks++)
        ldm4(sb + SM_A + (uint32_t)(Rb * 144 + ks * 32) + a_loff,
             afr[ks][0], afr[ks][1], afr[ks][2], afr[ks][3]);

    // ---- main loop: 8 chunks of 128 codes, double-buffered ----
    uint32_t K0[2] = {0, 0}, K1[2] = {0, 0};
    const int c = lane & 3;

    #pragma unroll 1
    for (int ch = 0; ch < 8; ch++) {
        if (ch == 7) cp_wait0(); else cp_wait1();
        __syncthreads();
        const uint32_t Bb = sb + SM_B + (uint32_t)((ch & 1) * 18432) + b_loff;
        const int cb0 = ch * 128 + 2 * c;

        #pragma unroll
        for (int nbp = 0; nbp < 8; nbp++) {
            uint32_t bk[4][4];
            #pragma unroll
            for (int ks = 0; ks < 4; ks++)
                ldm4(Bb + (uint32_t)(nbp * 2304 + ks * 32),
                     bk[ks][0], bk[ks][1], bk[ks][2], bk[ks][3]);
            // bias pre-loaded into MMA accumulators (no FADD epilogue)
            int col0 = cb0 + nbp * 16;
            float2 bb0 = *(const float2*)(bsm + col0);
            float2 bb1 = *(const float2*)(bsm + col0 + 8);
            float acc0[4] = {bb0.x, bb0.y, bb0.x, bb0.y};
            float acc1[4] = {bb1.x, bb1.y, bb1.x, bb1.y};
            #pragma unroll
            for (int ks = 0; ks < 4; ks++) {
                mma16816(acc0, afr[ks], bk[ks][0], bk[ks][1]);
                mma16816(acc1, afr[ks], bk[ks][2], bk[ks][3]);
            }
            // branch-free epilogue: packed key -> top-2 (4 alu ops/score)
            uint32_t inv = (uint32_t)(1023 - col0);
            ins2u(K0, pkkey(acc0[0], inv));
            ins2u(K0, pkkey(acc0[1], inv - 1));
            ins2u(K0, pkkey(acc1[0], inv - 8));
            ins2u(K0, pkkey(acc1[1], inv - 9));
            ins2u(K1, pkkey(acc0[2], inv));
            ins2u(K1, pkkey(acc0[3], inv - 1));
            ins2u(K1, pkkey(acc1[2], inv - 8));
            ins2u(K1, pkkey(acc1[3], inv - 9));
        }
        __syncthreads();
        if (ch < 6) {                          // prefetch chunk ch+2
            int pc = ch + 2;
            #pragma unroll
            for (int i = 0; i < 4; i++) {
                int idx = tid + i * 256;
                int r = idx >> 3, seg = idx & 7;
                cp16(sb + SM_B + (pc & 1) * 18432 + r * 144 + seg * 16,
                     bh + ((size_t)(pc * 128 + r)) * DIM + seg * 8);
            }
            cp_commit();
        }
    }

    // ---- quad merge: row best / margin / candidate dump ----
    const int g = lane >> 2;
    #pragma unroll
    for (int h = 0; h < 2; h++) {
        uint32_t* K = h ? K1 : K0;
        int row = Rb + 8 * h + g;
        uint32_t bs = K[0];
        bs = umax(bs, __shfl_xor_sync(0xffffffffu, bs, 1));
        bs = umax(bs, __shfl_xor_sync(0xffffffffu, bs, 2));
        uint32_t sc = (K[0] == bs) ? K[1] : K[0];
        sc = umax(sc, __shfl_xor_sync(0xffffffffu, sc, 1));
        sc = umax(sc, __shfl_xor_sync(0xffffffffu, sc, 2));
        cand[row * 8 + 2 * c]     = (uint16_t)(1023u - (K[0] & 1023u));
        cand[row * 8 + 2 * c + 1] = (uint16_t)(1023u - (K[1] & 1023u));
        if (c == 0) {
            isw[row] = (int)(1023u - (bs & 1023u));
            float mf = __uint_as_float(bs & 0xFFFFFC00u)
                     - __uint_as_float(sc & 0xFFFFFC00u);
            if (mf < THRESH) { int p = atomicAdd(cnt, 1); list[p] = row; }
        }
    }
    __syncthreads();

    // ---- fp64 rescue of tight rows (8 candidates each, warp per row) ----
    int nflag = *cnt;
    for (int e = wid; e < nflag; e += 8) {
        int row = list[e];
        double scv = -1e300; int kk = 0x7fffffff;
        if (lane < 8) {
            kk = (int)cand[row * 8 + lane];
            float rn = rnsm[row];
            const float* cp = g_cnf + (size_t)kk * DIM;
            const float* xr = x + (size_t)(row0 + row) * DIM;
            double d0 = 0, d1 = 0, d2 = 0, d3 = 0;
            #pragma unroll
            for (int j = 0; j < DIM; j += 4) {
                d0 += (double)(xr[j]     / rn) * (double)cp[j];
                d1 += (double)(xr[j + 1] / rn) * (double)cp[j + 1];
                d2 += (double)(xr[j + 2] / rn) * (double)cp[j + 2];
                d3 += (double)(xr[j + 3] / rn) * (double)cp[j + 3];
            }
            scv = ((d0 + d1) + (d2 + d3)) - g_biasd[kk];
        }
        #pragma unroll
        for (int off = 1; off <= 8; off <<= 1) {
            double os = __shfl_xor_sync(0xffffffffu, scv, off);
            int    oi = __shfl_xor_sync(0xffffffffu, kk, off);
            if (os > scv || (os == scv && oi < kk)) { scv = os; kk = oi; }
        }
        if (lane == 0) isw[row] = kk;
    }
    __syncthreads();

    // ---- outputs: STE quantized + indices + partial SSE ----
    const float4* xg4 = (const float4*)(x + (size_t)row0 * DIM);
    float4*       og4 = (float4*)(out + (size_t)row0 * DIM);
    float sse = 0.f;
    #pragma unroll
    for (int i = 0; i < 8; i++) {
        int e4 = tid + i * 256;                // 0..2047 float4
        int r = e4 >> 4, c4 = e4 & 15;
        int k = isw[r];
        float4 xv = xg4[e4];
        float4 q  = *(const float4*)(cb + (size_t)k * DIM + c4 * 4);
        float4 o; float d;
        d = q.x - xv.x; sse += d * d; o.x = xv.x + d;
        d = q.y - xv.y; sse += d * d; o.y = xv.y + d;
        d = q.z - xv.z; sse += d * d; o.z = xv.z + d;
        d = q.w - xv.w; sse += d * d; o.w = xv.w + d;
        og4[e4] = o;
    }
    if (tid < 128) out[(size_t)NQ + 2 + row0 + tid] = (float)isw[tid];

    #pragma unroll
    for (int o = 16; o > 0; o >>= 1) sse += __shfl_xor_sync(0xffffffffu, sse, o);
    if (lane == 0) red[wid] = sse;
    __syncthreads();
    if (tid == 0) {
        float t = 0.f;
        #pragma unroll
        for (int w = 0; w < 8; w++) t += red[w];
        g_partials[blockIdx.x] = t;
    }
}

// ============================================================================
// Kernel 3: reduce partials -> both losses
// ============================================================================
__global__ void vq_fin(float* __restrict__ out) {
    __shared__ float red[8];
    int tid = threadIdx.x;
    float s = 0.f;
    #pragma unroll
    for (int i = 0; i < 8; i++) s += g_partials[tid + i * 256];
    #pragma unroll
    for (int o = 16; o > 0; o >>= 1) s += __shfl_xor_sync(0xffffffffu, s, o);
    if ((tid & 31) == 0) red[tid >> 5] = s;
    __syncthreads();
    if (tid == 0) {
        float t = 0.f;
        #pragma unroll
        for (int w = 0; w < 8; w++) t += red[w];
        float loss = t / 16777216.0f;
        out[NQ]     = loss;   // codebook_loss
        out[NQ + 1] = loss;   // commitment_loss
    }
}

// ============================================================================
extern "C" void kernel_launch(void* const* d_in, const int* in_sizes, int n_in,
                              void* d_out, int out_size) {
    const float* x;
    const float* cb;
    if (in_sizes[0] == NROWS * DIM) {
        x  = (const float*)d_in[0];
        cb = (const float*)d_in[1];
    } else {
        x  = (const float*)d_in[1];
        cb = (const float*)d_in[0];
    }
    float* out = (float*)d_out;

    cudaFuncSetAttribute(vq_main, cudaFuncAttributeMaxDynamicSharedMemorySize, SM_TOTAL);

    vq_prep<<<128, 256>>>(cb);
    vq_main<<<TILES, 256, SM_TOTAL>>>(x, cb, out);
    vq_fin<<<1, 256>>>(out);
}